// round 3
// baseline (speedup 1.0000x reference)
#include <cuda_runtime.h>
#include <math.h>

#define ATOT   261888
#define CAND_M 21840
#define POSTK  1000
#define COMB   2618880
#define KB_OFF COMB
#define KS_OFF (COMB + 8000)
#define KV_OFF (COMB + 10000)
#define SCLAMP 4.135166556742356f
#define NEGINF (-__int_as_float(0x7f800000))

__constant__ int c_lvlbase[5] = {0,196608,245760,258048,261120};
__constant__ int c_lvlcnt[5]  = {196608,49152,12288,3072,768};
__constant__ int c_cslot[5]   = {0,6000,12000,18000,21072};
__constant__ int c_W[5]       = {256,128,64,32,16};
__constant__ int c_stride[5]  = {4,8,16,32,64};
__constant__ int c_size[5]    = {32,64,128,256,512};

__device__ float g_t[33554432];
__device__ float g_scores[2*ATOT];
__device__ float g_cscore[2*CAND_M];
__device__ float g_cbox[2*CAND_M*4];
__device__ float4 g_cobox[2*CAND_M];
__device__ float g_carea[2*CAND_M];
__device__ unsigned g_thr[6];
__device__ int g_need[6];

__device__ __forceinline__ unsigned fkey(float f) {
    unsigned u = __float_as_uint(f);
    return (u & 0x80000000u) ? ~u : (u | 0x80000000u);
}

// ---------------- conv3x3 + bias + relu ----------------
__global__ __launch_bounds__(256) void conv3x3_kernel(
    const float* __restrict__ x, const float* __restrict__ wgt,
    const float* __restrict__ bias, int H, int W)
{
    __shared__ float sW[16*9*64];
    __shared__ float sI[16*100];
    const int tid = threadIdx.x;
    const int n  = blockIdx.z >> 2;
    const int cb = blockIdx.z & 3;
    const int h0 = blockIdx.y * 8, w0 = blockIdx.x * 8;
    const int tx = tid & 15, ty = tid >> 4;
    const int r0 = ty >> 1, c0 = (ty & 1) * 4;
    const int HW = H * W;

    float acc[4][4];
    #pragma unroll
    for (int q = 0; q < 4; ++q)
        #pragma unroll
        for (int j = 0; j < 4; ++j) acc[q][j] = 0.f;

    for (int kc = 0; kc < 16; ++kc) {
        for (int i = tid; i < 9216; i += 256) {
            int co_l = i / 144; int j = i - co_l*144;
            int ci_l = j / 9;   int kk = j - ci_l*9;
            sW[(ci_l*9 + kk)*64 + co_l] =
                wgt[(size_t)(cb*64 + co_l)*2304 + (kc*16 + ci_l)*9 + kk];
        }
        for (int i = tid; i < 1600; i += 256) {
            int ci_l = i / 100; int p = i - ci_l*100;
            int r = p / 10, c = p - r*10;
            int gh = h0 - 1 + r, gw = w0 - 1 + c;
            float v = 0.f;
            if (gh >= 0 && gh < H && gw >= 0 && gw < W)
                v = x[(size_t)(n*256 + kc*16 + ci_l)*HW + gh*W + gw];
            sI[i] = v;
        }
        __syncthreads();
        #pragma unroll 4
        for (int ci = 0; ci < 16; ++ci) {
            #pragma unroll
            for (int kh = 0; kh < 3; ++kh) {
                #pragma unroll
                for (int kw = 0; kw < 3; ++kw) {
                    const float4 wv = *(const float4*)&sW[(ci*9 + kh*3 + kw)*64 + tx*4];
                    const float* ip = &sI[ci*100 + (r0 + kh)*10 + c0 + kw];
                    float i0 = ip[0], i1 = ip[1], i2 = ip[2], i3 = ip[3];
                    acc[0][0]=fmaf(wv.x,i0,acc[0][0]); acc[0][1]=fmaf(wv.x,i1,acc[0][1]);
                    acc[0][2]=fmaf(wv.x,i2,acc[0][2]); acc[0][3]=fmaf(wv.x,i3,acc[0][3]);
                    acc[1][0]=fmaf(wv.y,i0,acc[1][0]); acc[1][1]=fmaf(wv.y,i1,acc[1][1]);
                    acc[1][2]=fmaf(wv.y,i2,acc[1][2]); acc[1][3]=fmaf(wv.y,i3,acc[1][3]);
                    acc[2][0]=fmaf(wv.z,i0,acc[2][0]); acc[2][1]=fmaf(wv.z,i1,acc[2][1]);
                    acc[2][2]=fmaf(wv.z,i2,acc[2][2]); acc[2][3]=fmaf(wv.z,i3,acc[2][3]);
                    acc[3][0]=fmaf(wv.w,i0,acc[3][0]); acc[3][1]=fmaf(wv.w,i1,acc[3][1]);
                    acc[3][2]=fmaf(wv.w,i2,acc[3][2]); acc[3][3]=fmaf(wv.w,i3,acc[3][3]);
                }
            }
        }
        __syncthreads();
    }
    const int h = h0 + r0, w = w0 + c0;
    #pragma unroll
    for (int q = 0; q < 4; ++q) {
        int co = cb*64 + tx*4 + q;
        float bv = bias[co];
        float4 r;
        r.x = fmaxf(acc[q][0] + bv, 0.f);
        r.y = fmaxf(acc[q][1] + bv, 0.f);
        r.z = fmaxf(acc[q][2] + bv, 0.f);
        r.w = fmaxf(acc[q][3] + bv, 0.f);
        *(float4*)&g_t[(size_t)(n*256 + co)*HW + h*W + w] = r;
    }
}

// ---------------- 1x1 heads ----------------
__global__ __launch_bounds__(256) void head1x1_kernel(
    const float* __restrict__ objw, const float* __restrict__ objb,
    const float* __restrict__ dlw,  const float* __restrict__ dlb,
    float* __restrict__ comb, int H, int W, int gbase)
{
    __shared__ float sw[15*256];
    __shared__ float sb[15];
    int tid = threadIdx.x;
    for (int i = tid; i < 3*256; i += 256)  sw[i] = objw[i];
    for (int i = tid; i < 12*256; i += 256) sw[768 + i] = dlw[i];
    if (tid < 3)  sb[tid] = objb[tid];
    if (tid >= 3 && tid < 15) sb[tid] = dlb[tid - 3];
    __syncthreads();

    int pid = blockIdx.x * 256 + tid;
    int HW = H * W;
    if (pid >= 2 * HW) return;
    int n = pid / HW, hw = pid - n*HW;

    float acc[15];
    #pragma unroll
    for (int k = 0; k < 15; ++k) acc[k] = sb[k];
    const float* tp = &g_t[(size_t)n*256*HW + hw];
    for (int c = 0; c < 256; ++c) {
        float tv = tp[(size_t)c * HW];
        #pragma unroll
        for (int k = 0; k < 15; ++k) acc[k] = fmaf(tv, sw[k*256 + c], acc[k]);
    }
    #pragma unroll
    for (int a = 0; a < 3; ++a) {
        int ga = gbase + hw*3 + a;
        size_t o = ((size_t)n*ATOT + ga)*5;
        comb[o]   = acc[a];
        comb[o+1] = acc[3 + a*4 + 0];
        comb[o+2] = acc[3 + a*4 + 1];
        comb[o+3] = acc[3 + a*4 + 2];
        comb[o+4] = acc[3 + a*4 + 3];
        g_scores[(size_t)n*ATOT + ga] = acc[a];
    }
}

// ---------------- exact top-6000 threshold (radix refine) ----------------
__global__ __launch_bounds__(1024) void select_kernel() {
    int task = blockIdx.x;       // n*3 + lvl, lvl in 0..2
    int n = task / 3, lvl = task % 3;
    const float* d = g_scores + (size_t)n*ATOT + c_lvlbase[lvl];
    int cnt = c_lvlcnt[lvl];
    int tid = threadIdx.x;
    __shared__ int hist[256];
    __shared__ unsigned s_prefix;
    __shared__ int s_Kr;
    if (tid == 0) { s_prefix = 0; s_Kr = 6000; }
    __syncthreads();
    for (int pass = 0; pass < 4; ++pass) {
        int shift = 24 - pass*8;
        if (tid < 256) hist[tid] = 0;
        __syncthreads();
        unsigned pref = s_prefix;
        for (int i = tid; i < cnt; i += 1024) {
            unsigned k = fkey(d[i]);
            bool in = (pass == 0) || ((k >> (shift + 8)) == pref);
            if (in) atomicAdd(&hist[(k >> shift) & 255], 1);
        }
        __syncthreads();
        if (tid == 0) {
            int run = 0, dd = 255;
            for (dd = 255; dd >= 0; --dd) {
                if (run + hist[dd] >= s_Kr) break;
                run += hist[dd];
            }
            s_prefix = (s_prefix << 8) | (unsigned)dd;
            s_Kr -= run;
        }
        __syncthreads();
    }
    if (tid == 0) { g_thr[task] = s_prefix; g_need[task] = s_Kr; }
}

// ---------------- stable compaction + decode ----------------
__device__ __forceinline__ int blockScan01(int pred, int tid, int* ws, int* tot) {
    unsigned b = __ballot_sync(0xffffffffu, pred != 0);
    int lane = tid & 31, wid = tid >> 5;
    int lpre = __popc(b & ((1u << lane) - 1u));
    if (lane == 0) ws[wid] = __popc(b);
    __syncthreads();
    if (tid < 32) {
        int v = ws[tid];
        int s = v;
        #pragma unroll
        for (int o = 1; o < 32; o <<= 1) {
            int t = __shfl_up_sync(0xffffffffu, s, o);
            if (tid >= o) s += t;
        }
        ws[tid] = s - v;
        if (tid == 31) ws[32] = s;
    }
    __syncthreads();
    int ex = ws[wid] + lpre;
    *tot = ws[32];
    __syncthreads();
    return ex;
}

__global__ __launch_bounds__(1024) void compact_kernel(const float* __restrict__ comb) {
    int n = blockIdx.x / 5, lvl = blockIdx.x % 5;
    int tid = threadIdx.x;
    __shared__ int ws[33];
    unsigned T = 0; int need = 0;
    if (lvl < 3) { T = g_thr[n*3 + lvl]; need = g_need[n*3 + lvl]; }
    const float* sc = g_scores + (size_t)n*ATOT + c_lvlbase[lvl];
    int cnt = c_lvlcnt[lvl];
    int outBase = n*CAND_M + c_cslot[lvl];
    int gbase = c_lvlbase[lvl];
    int Wl = c_W[lvl], str = c_stride[lvl];
    double sz = (double)c_size[lvl];
    int eqBefore = 0, written = 0;
    for (int start = 0; start < cnt; start += 1024) {
        int i = start + tid;
        bool inb = (i < cnt);
        unsigned k = inb ? fkey(sc[i]) : 0u;
        int pEQ = (inb && k == T) ? 1 : 0;
        int totEQ; int exEQ = blockScan01(pEQ, tid, ws, &totEQ);
        int sel = (inb && (k > T || (pEQ && (eqBefore + exEQ) < need))) ? 1 : 0;
        int totS; int exS = blockScan01(sel, tid, ws, &totS);
        if (sel) {
            int slot = outBase + written + exS;
            int hw = i / 3, a = i - hw*3;
            int h = hw / Wl, w = hw - h*Wl;
            double r = (a == 0) ? 0.5 : ((a == 1) ? 1.0 : 2.0);
            double wsd = sqrt(sz*sz/r);
            double hsd = wsd*r;
            double xx = (double)(w * str), yy = (double)(h * str);
            float a0 = (float)(xx - wsd*0.5);
            float a1 = (float)(yy - hsd*0.5);
            float a2 = (float)(xx + wsd*0.5);
            float a3 = (float)(yy + hsd*0.5);
            size_t o = ((size_t)n*ATOT + gbase + i)*5;
            float dx = comb[o+1], dy = comb[o+2];
            float dw = fminf(comb[o+3], SCLAMP), dh = fminf(comb[o+4], SCLAMP);
            float aw = a2 - a0, ah = a3 - a1;
            float cx = a0 + 0.5f*aw, cy = a1 + 0.5f*ah;
            float pcx = dx*aw + cx, pcy = dy*ah + cy;
            float pw = expf(dw)*aw, ph = expf(dh)*ah;
            float x1 = pcx - 0.5f*pw, y1 = pcy - 0.5f*ph;
            float x2 = pcx + 0.5f*pw, y2 = pcy + 0.5f*ph;
            x1 = fminf(fmaxf(x1, 0.f), 1024.f);
            y1 = fminf(fmaxf(y1, 0.f), 1024.f);
            x2 = fminf(fmaxf(x2, 0.f), 1024.f);
            y2 = fminf(fmaxf(y2, 0.f), 1024.f);
            g_cbox[slot*4+0] = x1; g_cbox[slot*4+1] = y1;
            g_cbox[slot*4+2] = x2; g_cbox[slot*4+3] = y2;
            float off = (float)lvl * 2000.0f;
            float o0 = x1 + off, o1 = y1 + off, o2 = x2 + off, o3 = y2 + off;
            g_cobox[slot] = make_float4(o0, o1, o2, o3);
            g_carea[slot] = (o2 - o0) * (o3 - o1);
            g_cscore[slot] = sc[i];
        }
        eqBefore += totEQ; written += totS;
    }
}

// ---------------- argmax-NMS (exact scan semantics) ----------------
__global__ __launch_bounds__(1024) void nms_kernel(float* __restrict__ out) {
    extern __shared__ float s[];        // CAND_M live scores
    __shared__ float rv[32]; __shared__ int ri[32];
    __shared__ float s_bv; __shared__ int s_bi; __shared__ int s_fb;
    int n = blockIdx.x, tid = threadIdx.x;
    int base = n * CAND_M;
    for (int j = tid; j < CAND_M; j += 1024) s[j] = g_cscore[base + j];
    __syncthreads();

    // fallback = argmax over level-0 slots [0,6000) (candidate position 0 in ref)
    {
        float bv = NEGINF; int bi = 0x7fffffff;
        for (int j = tid; j < 6000; j += 1024) {
            float v = s[j];
            if (v > bv) { bv = v; bi = j; }
            else if (v == bv && j < bi) bi = j;
        }
        #pragma unroll
        for (int o = 16; o; o >>= 1) {
            float ov = __shfl_down_sync(0xffffffffu, bv, o);
            int oi = __shfl_down_sync(0xffffffffu, bi, o);
            if (ov > bv || (ov == bv && oi < bi)) { bv = ov; bi = oi; }
        }
        if ((tid & 31) == 0) { rv[tid >> 5] = bv; ri[tid >> 5] = bi; }
        __syncthreads();
        if (tid < 32) {
            bv = rv[tid]; bi = ri[tid];
            #pragma unroll
            for (int o = 16; o; o >>= 1) {
                float ov = __shfl_down_sync(0xffffffffu, bv, o);
                int oi = __shfl_down_sync(0xffffffffu, bi, o);
                if (ov > bv || (ov == bv && oi < bi)) { bv = ov; bi = oi; }
            }
            if (tid == 0) s_fb = bi;
        }
        __syncthreads();
    }

    float* kb = out + KB_OFF + (size_t)n*POSTK*4;
    float* ks = out + KS_OFF + (size_t)n*POSTK;
    float* kv = out + KV_OFF + (size_t)n*POSTK;

    for (int iter = 0; iter < POSTK; ++iter) {
        // block argmax, tie -> lowest index
        float bv = NEGINF; int bi = 0x7fffffff;
        for (int j = tid; j < CAND_M; j += 1024) {
            float v = s[j];
            if (v > bv) { bv = v; bi = j; }
            else if (v == bv && j < bi) bi = j;
        }
        #pragma unroll
        for (int o = 16; o; o >>= 1) {
            float ov = __shfl_down_sync(0xffffffffu, bv, o);
            int oi = __shfl_down_sync(0xffffffffu, bi, o);
            if (ov > bv || (ov == bv && oi < bi)) { bv = ov; bi = oi; }
        }
        if ((tid & 31) == 0) { rv[tid >> 5] = bv; ri[tid >> 5] = bi; }
        __syncthreads();
        if (tid < 32) {
            bv = rv[tid]; bi = ri[tid];
            #pragma unroll
            for (int o = 16; o; o >>= 1) {
                float ov = __shfl_down_sync(0xffffffffu, bv, o);
                int oi = __shfl_down_sync(0xffffffffu, bi, o);
                if (ov > bv || (ov == bv && oi < bi)) { bv = ov; bi = oi; }
            }
            if (tid == 0) { s_bv = bv; s_bi = bi; }
        }
        __syncthreads();
        bv = s_bv; bi = s_bi;
        bool valid = (bv > NEGINF);
        int src = valid ? bi : s_fb;
        if (tid == 0) {
            kb[iter*4+0] = g_cbox[(base+src)*4+0];
            kb[iter*4+1] = g_cbox[(base+src)*4+1];
            kb[iter*4+2] = g_cbox[(base+src)*4+2];
            kb[iter*4+3] = g_cbox[(base+src)*4+3];
            ks[iter] = g_cscore[base+src];
            kv[iter] = valid ? 1.0f : 0.0f;
        }
        if (valid) {
            float4 bb = g_cobox[base + bi];
            float ai = g_carea[base + bi];
            for (int j = tid; j < CAND_M; j += 1024) {
                float v = s[j];
                if (v > NEGINF) {
                    float4 cj = g_cobox[base + j];
                    float x1 = fmaxf(bb.x, cj.x), y1 = fmaxf(bb.y, cj.y);
                    float x2 = fminf(bb.z, cj.z), y2 = fminf(bb.w, cj.w);
                    float inter = fmaxf(x2 - x1, 0.f) * fmaxf(y2 - y1, 0.f);
                    float iou = inter / (ai + g_carea[base + j] - inter + 1e-9f);
                    if (iou > 0.7f) s[j] = NEGINF;
                }
            }
        }
        if (tid == 0) s[bi] = NEGINF;
        __syncthreads();
    }
}

extern "C" void kernel_launch(void* const* d_in, const int* in_sizes, int n_in,
                              void* d_out, int out_size) {
    const float* feats[5] = {(const float*)d_in[0], (const float*)d_in[1],
                             (const float*)d_in[2], (const float*)d_in[3],
                             (const float*)d_in[4]};
    const float* conv_w = (const float*)d_in[5];
    const float* conv_b = (const float*)d_in[6];
    const float* obj_w  = (const float*)d_in[7];
    const float* obj_b  = (const float*)d_in[8];
    const float* dl_w   = (const float*)d_in[9];
    const float* dl_b   = (const float*)d_in[10];
    float* out = (float*)d_out;

    static const int HH[5] = {256,128,64,32,16};
    static const int WW[5] = {256,128,64,32,16};
    static const int BB[5] = {0,196608,245760,258048,261120};

    for (int l = 0; l < 5; ++l) {
        dim3 g(WW[l]/8, HH[l]/8, 8);
        conv3x3_kernel<<<g, 256>>>(feats[l], conv_w, conv_b, HH[l], WW[l]);
        int px = 2 * HH[l] * WW[l];
        head1x1_kernel<<<(px + 255)/256, 256>>>(obj_w, obj_b, dl_w, dl_b,
                                                out, HH[l], WW[l], BB[l]);
    }
    select_kernel<<<6, 1024>>>();
    compact_kernel<<<10, 1024>>>(out);
    cudaFuncSetAttribute(nms_kernel, cudaFuncAttributeMaxDynamicSharedMemorySize,
                         CAND_M * (int)sizeof(float));
    nms_kernel<<<2, 1024, CAND_M * sizeof(float)>>>(out);
}

// round 5
// speedup vs baseline: 2.7762x; 2.7762x over previous
#include <cuda_runtime.h>
#include <math.h>

#define ATOT   261888
#define CAND_M 21840
#define POSTK  1000
#define COMB   2618880
#define KB_OFF COMB
#define KS_OFF (COMB + 8000)
#define KV_OFF (COMB + 10000)
#define SCLAMP 4.135166556742356f
#define NEGINF (-__int_as_float(0x7f800000))

__constant__ int c_lvlbase[5] = {0,196608,245760,258048,261120};
__constant__ int c_lvlcnt[5]  = {196608,49152,12288,3072,768};
__constant__ int c_cslot[5]   = {0,6000,12000,18000,21072};
__constant__ int c_W[5]       = {256,128,64,32,16};
__constant__ int c_stride[5]  = {4,8,16,32,64};
__constant__ int c_size[5]    = {32,64,128,256,512};

__device__ float g_t[33554432];
__device__ float g_scores[2*ATOT];
__device__ float g_cscore[2*CAND_M];
__device__ float g_cbox[2*CAND_M*4];
__device__ float4 g_cobox[2*CAND_M];
__device__ float g_carea[2*CAND_M];
__device__ unsigned g_thr[6];
__device__ int g_need[6];

__device__ __forceinline__ unsigned fkey(float f) {
    unsigned u = __float_as_uint(f);
    return (u & 0x80000000u) ? ~u : (u | 0x80000000u);
}

// ---------------- conv3x3 + bias + relu ----------------
// block: 256 thr = 16 (cout groups of 4) x 16 (4x4 pixel subtiles)
// tile per block: 64 couts x 16x16 pixels
#define CONV_SMEM ((16*9*64 + 16*360)*4)
__global__ __launch_bounds__(256, 2) void conv3x3_kernel(
    const float* __restrict__ x, const float* __restrict__ wgt,
    const float* __restrict__ bias, int H, int W)
{
    extern __shared__ float sm[];
    float* sW = sm;             // [ci][9][64]  : 9216 floats
    float* sI = sm + 9216;      // [ci][18 rows][pitch 20] : 5760 floats

    const int tid = threadIdx.x;
    const int n  = blockIdx.z >> 2;
    const int cb = blockIdx.z & 3;
    const int h0 = blockIdx.y * 16, w0 = blockIdx.x * 16;
    const int tx = tid & 15, ty = tid >> 4;
    const int pr0 = (ty >> 2) * 4, pc0 = (ty & 3) * 4;
    const int HW = H * W;

    float acc[4][16];
    #pragma unroll
    for (int q = 0; q < 4; ++q)
        #pragma unroll
        for (int j = 0; j < 16; ++j) acc[q][j] = 0.f;

    for (int kc = 0; kc < 16; ++kc) {
        // weights: 64 couts x 16 cins x 9 taps
        #pragma unroll
        for (int it = 0; it < 36; ++it) {
            int i = tid + it*256;
            int co_l = i / 144; int j = i - co_l*144;
            int ci_l = j / 9;   int kk = j - ci_l*9;
            sW[(ci_l*9 + kk)*64 + co_l] =
                wgt[(size_t)(cb*64 + co_l)*2304 + (kc*16 + ci_l)*9 + kk];
        }
        // input: 16 cins x 18x18 (halo 1), pitch 20
        for (int i = tid; i < 16*18*18; i += 256) {
            int ci_l = i / 324; int p = i - ci_l*324;
            int r = p / 18, c = p - r*18;
            int gh = h0 - 1 + r, gw = w0 - 1 + c;
            float v = 0.f;
            if (gh >= 0 && gh < H && gw >= 0 && gw < W)
                v = x[(size_t)(n*256 + kc*16 + ci_l)*HW + gh*W + gw];
            sI[ci_l*360 + r*20 + c] = v;
        }
        __syncthreads();

        #pragma unroll 1
        for (int ci = 0; ci < 16; ++ci) {
            float in[6][6];
            const float* ib = &sI[ci*360 + pr0*20 + pc0];
            #pragma unroll
            for (int rr = 0; rr < 6; ++rr)
                #pragma unroll
                for (int cc = 0; cc < 6; ++cc)
                    in[rr][cc] = ib[rr*20 + cc];
            const float* wb = &sW[ci*9*64 + tx*4];
            #pragma unroll
            for (int kh = 0; kh < 3; ++kh) {
                #pragma unroll
                for (int kw = 0; kw < 3; ++kw) {
                    const float4 w4 = *(const float4*)&wb[(kh*3 + kw)*64];
                    #pragma unroll
                    for (int pr = 0; pr < 4; ++pr) {
                        #pragma unroll
                        for (int pc = 0; pc < 4; ++pc) {
                            float v = in[pr + kh][pc + kw];
                            acc[0][pr*4+pc] = fmaf(w4.x, v, acc[0][pr*4+pc]);
                            acc[1][pr*4+pc] = fmaf(w4.y, v, acc[1][pr*4+pc]);
                            acc[2][pr*4+pc] = fmaf(w4.z, v, acc[2][pr*4+pc]);
                            acc[3][pr*4+pc] = fmaf(w4.w, v, acc[3][pr*4+pc]);
                        }
                    }
                }
            }
        }
        __syncthreads();
    }

    #pragma unroll
    for (int q = 0; q < 4; ++q) {
        int co = cb*64 + tx*4 + q;
        float bv = bias[co];
        #pragma unroll
        for (int pr = 0; pr < 4; ++pr) {
            float4 r;
            r.x = fmaxf(acc[q][pr*4+0] + bv, 0.f);
            r.y = fmaxf(acc[q][pr*4+1] + bv, 0.f);
            r.z = fmaxf(acc[q][pr*4+2] + bv, 0.f);
            r.w = fmaxf(acc[q][pr*4+3] + bv, 0.f);
            *(float4*)&g_t[(size_t)(n*256 + co)*HW + (h0+pr0+pr)*W + w0+pc0] = r;
        }
    }
}

// ---------------- 1x1 heads ----------------
__global__ __launch_bounds__(256) void head1x1_kernel(
    const float* __restrict__ objw, const float* __restrict__ objb,
    const float* __restrict__ dlw,  const float* __restrict__ dlb,
    float* __restrict__ comb, int H, int W, int gbase)
{
    __shared__ float sw[15*256];
    __shared__ float sb[15];
    int tid = threadIdx.x;
    for (int i = tid; i < 3*256; i += 256)  sw[i] = objw[i];
    for (int i = tid; i < 12*256; i += 256) sw[768 + i] = dlw[i];
    if (tid < 3)  sb[tid] = objb[tid];
    if (tid >= 3 && tid < 15) sb[tid] = dlb[tid - 3];
    __syncthreads();

    int pid = blockIdx.x * 256 + tid;
    int HW = H * W;
    if (pid >= 2 * HW) return;
    int n = pid / HW, hw = pid - n*HW;

    float acc[15];
    #pragma unroll
    for (int k = 0; k < 15; ++k) acc[k] = sb[k];
    const float* tp = &g_t[(size_t)n*256*HW + hw];
    #pragma unroll 4
    for (int c = 0; c < 256; ++c) {
        float tv = __ldg(&tp[(size_t)c * HW]);
        #pragma unroll
        for (int k = 0; k < 15; ++k) acc[k] = fmaf(tv, sw[k*256 + c], acc[k]);
    }
    #pragma unroll
    for (int a = 0; a < 3; ++a) {
        int ga = gbase + hw*3 + a;
        size_t o = ((size_t)n*ATOT + ga)*5;
        comb[o]   = acc[a];
        comb[o+1] = acc[3 + a*4 + 0];
        comb[o+2] = acc[3 + a*4 + 1];
        comb[o+3] = acc[3 + a*4 + 2];
        comb[o+4] = acc[3 + a*4 + 3];
        g_scores[(size_t)n*ATOT + ga] = acc[a];
    }
}

// ---------------- exact top-6000 threshold (radix refine) ----------------
__global__ __launch_bounds__(1024) void select_kernel() {
    int task = blockIdx.x;       // n*3 + lvl, lvl in 0..2
    int n = task / 3, lvl = task % 3;
    const float* d = g_scores + (size_t)n*ATOT + c_lvlbase[lvl];
    int cnt = c_lvlcnt[lvl];
    int tid = threadIdx.x;
    __shared__ int hist[256];
    __shared__ unsigned s_prefix;
    __shared__ int s_Kr;
    if (tid == 0) { s_prefix = 0; s_Kr = 6000; }
    __syncthreads();
    for (int pass = 0; pass < 4; ++pass) {
        int shift = 24 - pass*8;
        if (tid < 256) hist[tid] = 0;
        __syncthreads();
        unsigned pref = s_prefix;
        for (int i = tid; i < cnt; i += 1024) {
            unsigned k = fkey(d[i]);
            bool in = (pass == 0) || ((k >> (shift + 8)) == pref);
            if (in) atomicAdd(&hist[(k >> shift) & 255], 1);
        }
        __syncthreads();
        if (tid == 0) {
            int run = 0, dd = 255;
            for (dd = 255; dd >= 0; --dd) {
                if (run + hist[dd] >= s_Kr) break;
                run += hist[dd];
            }
            s_prefix = (s_prefix << 8) | (unsigned)dd;
            s_Kr -= run;
        }
        __syncthreads();
    }
    if (tid == 0) { g_thr[task] = s_prefix; g_need[task] = s_Kr; }
}

// ---------------- stable compaction + decode ----------------
__device__ __forceinline__ int blockScan01(int pred, int tid, int* ws, int* tot) {
    unsigned b = __ballot_sync(0xffffffffu, pred != 0);
    int lane = tid & 31, wid = tid >> 5;
    int lpre = __popc(b & ((1u << lane) - 1u));
    if (lane == 0) ws[wid] = __popc(b);
    __syncthreads();
    if (tid < 32) {
        int v = ws[tid];
        int s = v;
        #pragma unroll
        for (int o = 1; o < 32; o <<= 1) {
            int t = __shfl_up_sync(0xffffffffu, s, o);
            if (tid >= o) s += t;
        }
        ws[tid] = s - v;
        if (tid == 31) ws[32] = s;
    }
    __syncthreads();
    int ex = ws[wid] + lpre;
    *tot = ws[32];
    __syncthreads();
    return ex;
}

__global__ __launch_bounds__(1024) void compact_kernel(const float* __restrict__ comb) {
    int n = blockIdx.x / 5, lvl = blockIdx.x % 5;
    int tid = threadIdx.x;
    __shared__ int ws[33];
    unsigned T = 0; int need = 0;
    if (lvl < 3) { T = g_thr[n*3 + lvl]; need = g_need[n*3 + lvl]; }
    const float* sc = g_scores + (size_t)n*ATOT + c_lvlbase[lvl];
    int cnt = c_lvlcnt[lvl];
    int outBase = n*CAND_M + c_cslot[lvl];
    int gbase = c_lvlbase[lvl];
    int Wl = c_W[lvl], str = c_stride[lvl];
    double sz = (double)c_size[lvl];
    int eqBefore = 0, written = 0;
    for (int start = 0; start < cnt; start += 1024) {
        int i = start + tid;
        bool inb = (i < cnt);
        unsigned k = inb ? fkey(sc[i]) : 0u;
        int pEQ = (inb && k == T) ? 1 : 0;
        int totEQ; int exEQ = blockScan01(pEQ, tid, ws, &totEQ);
        int sel = (inb && (k > T || (pEQ && (eqBefore + exEQ) < need))) ? 1 : 0;
        int totS; int exS = blockScan01(sel, tid, ws, &totS);
        if (sel) {
            int slot = outBase + written + exS;
            int hw = i / 3, a = i - hw*3;
            int h = hw / Wl, w = hw - h*Wl;
            double r = (a == 0) ? 0.5 : ((a == 1) ? 1.0 : 2.0);
            double wsd = sqrt(sz*sz/r);
            double hsd = wsd*r;
            double xx = (double)(w * str), yy = (double)(h * str);
            float a0 = (float)(xx - wsd*0.5);
            float a1 = (float)(yy - hsd*0.5);
            float a2 = (float)(xx + wsd*0.5);
            float a3 = (float)(yy + hsd*0.5);
            size_t o = ((size_t)n*ATOT + gbase + i)*5;
            float dx = comb[o+1], dy = comb[o+2];
            float dw = fminf(comb[o+3], SCLAMP), dh = fminf(comb[o+4], SCLAMP);
            float aw = a2 - a0, ah = a3 - a1;
            float cx = a0 + 0.5f*aw, cy = a1 + 0.5f*ah;
            float pcx = dx*aw + cx, pcy = dy*ah + cy;
            float pw = expf(dw)*aw, ph = expf(dh)*ah;
            float x1 = pcx - 0.5f*pw, y1 = pcy - 0.5f*ph;
            float x2 = pcx + 0.5f*pw, y2 = pcy + 0.5f*ph;
            x1 = fminf(fmaxf(x1, 0.f), 1024.f);
            y1 = fminf(fmaxf(y1, 0.f), 1024.f);
            x2 = fminf(fmaxf(x2, 0.f), 1024.f);
            y2 = fminf(fmaxf(y2, 0.f), 1024.f);
            g_cbox[slot*4+0] = x1; g_cbox[slot*4+1] = y1;
            g_cbox[slot*4+2] = x2; g_cbox[slot*4+3] = y2;
            float off = (float)lvl * 2000.0f;
            float o0 = x1 + off, o1 = y1 + off, o2 = x2 + off, o3 = y2 + off;
            g_cobox[slot] = make_float4(o0, o1, o2, o3);
            g_carea[slot] = (o2 - o0) * (o3 - o1);
            g_cscore[slot] = sc[i];
        }
        eqBefore += totEQ; written += totS;
    }
}

// ---------------- argmax-NMS (exact scan semantics) ----------------
__global__ __launch_bounds__(1024) void nms_kernel(float* __restrict__ out) {
    extern __shared__ float s[];        // CAND_M live scores
    __shared__ float rv[32]; __shared__ int ri[32];
    __shared__ float s_bv; __shared__ int s_bi; __shared__ int s_fb;
    int n = blockIdx.x, tid = threadIdx.x;
    int base = n * CAND_M;
    for (int j = tid; j < CAND_M; j += 1024) s[j] = g_cscore[base + j];
    __syncthreads();

    // fallback = argmax over level-0 slots [0,6000)
    {
        float bv = NEGINF; int bi = 0x7fffffff;
        for (int j = tid; j < 6000; j += 1024) {
            float v = s[j];
            if (v > bv) { bv = v; bi = j; }
            else if (v == bv && j < bi) bi = j;
        }
        #pragma unroll
        for (int o = 16; o; o >>= 1) {
            float ov = __shfl_down_sync(0xffffffffu, bv, o);
            int oi = __shfl_down_sync(0xffffffffu, bi, o);
            if (ov > bv || (ov == bv && oi < bi)) { bv = ov; bi = oi; }
        }
        if ((tid & 31) == 0) { rv[tid >> 5] = bv; ri[tid >> 5] = bi; }
        __syncthreads();
        if (tid < 32) {
            bv = rv[tid]; bi = ri[tid];
            #pragma unroll
            for (int o = 16; o; o >>= 1) {
                float ov = __shfl_down_sync(0xffffffffu, bv, o);
                int oi = __shfl_down_sync(0xffffffffu, bi, o);
                if (ov > bv || (ov == bv && oi < bi)) { bv = ov; bi = oi; }
            }
            if (tid == 0) s_fb = bi;
        }
        __syncthreads();
    }

    float* kb = out + KB_OFF + (size_t)n*POSTK*4;
    float* ks = out + KS_OFF + (size_t)n*POSTK;
    float* kv = out + KV_OFF + (size_t)n*POSTK;

    for (int iter = 0; iter < POSTK; ++iter) {
        float bv = NEGINF; int bi = 0x7fffffff;
        for (int j = tid; j < CAND_M; j += 1024) {
            float v = s[j];
            if (v > bv) { bv = v; bi = j; }
            else if (v == bv && j < bi) bi = j;
        }
        #pragma unroll
        for (int o = 16; o; o >>= 1) {
            float ov = __shfl_down_sync(0xffffffffu, bv, o);
            int oi = __shfl_down_sync(0xffffffffu, bi, o);
            if (ov > bv || (ov == bv && oi < bi)) { bv = ov; bi = oi; }
        }
        if ((tid & 31) == 0) { rv[tid >> 5] = bv; ri[tid >> 5] = bi; }
        __syncthreads();
        if (tid < 32) {
            bv = rv[tid]; bi = ri[tid];
            #pragma unroll
            for (int o = 16; o; o >>= 1) {
                float ov = __shfl_down_sync(0xffffffffu, bv, o);
                int oi = __shfl_down_sync(0xffffffffu, bi, o);
                if (ov > bv || (ov == bv && oi < bi)) { bv = ov; bi = oi; }
            }
            if (tid == 0) { s_bv = bv; s_bi = bi; }
        }
        __syncthreads();
        bv = s_bv; bi = s_bi;
        bool valid = (bv > NEGINF);
        int src = valid ? bi : s_fb;
        if (tid == 0) {
            kb[iter*4+0] = g_cbox[(base+src)*4+0];
            kb[iter*4+1] = g_cbox[(base+src)*4+1];
            kb[iter*4+2] = g_cbox[(base+src)*4+2];
            kb[iter*4+3] = g_cbox[(base+src)*4+3];
            ks[iter] = g_cscore[base+src];
            kv[iter] = valid ? 1.0f : 0.0f;
        }
        if (valid) {
            // cross-level IoU is 0 by construction (+2000*lvl offsets) -> scan only bi's level
            int segLo, segHi;
            if      (bi < 6000)  { segLo = 0;     segHi = 6000;  }
            else if (bi < 12000) { segLo = 6000;  segHi = 12000; }
            else if (bi < 18000) { segLo = 12000; segHi = 18000; }
            else if (bi < 21072) { segLo = 18000; segHi = 21072; }
            else                 { segLo = 21072; segHi = 21840; }
            float4 bb = g_cobox[base + bi];
            float ai = g_carea[base + bi];
            for (int j = segLo + tid; j < segHi; j += 1024) {
                float v = s[j];
                if (v > NEGINF) {
                    float4 cj = g_cobox[base + j];
                    float x1 = fmaxf(bb.x, cj.x), y1 = fmaxf(bb.y, cj.y);
                    float x2 = fminf(bb.z, cj.z), y2 = fminf(bb.w, cj.w);
                    float inter = fmaxf(x2 - x1, 0.f) * fmaxf(y2 - y1, 0.f);
                    float iou = inter / (ai + g_carea[base + j] - inter + 1e-9f);
                    if (iou > 0.7f) s[j] = NEGINF;
                }
            }
        }
        if (tid == 0) s[bi] = NEGINF;
        __syncthreads();
    }
}

extern "C" void kernel_launch(void* const* d_in, const int* in_sizes, int n_in,
                              void* d_out, int out_size) {
    const float* feats[5] = {(const float*)d_in[0], (const float*)d_in[1],
                             (const float*)d_in[2], (const float*)d_in[3],
                             (const float*)d_in[4]};
    const float* conv_w = (const float*)d_in[5];
    const float* conv_b = (const float*)d_in[6];
    const float* obj_w  = (const float*)d_in[7];
    const float* obj_b  = (const float*)d_in[8];
    const float* dl_w   = (const float*)d_in[9];
    const float* dl_b   = (const float*)d_in[10];
    float* out = (float*)d_out;

    static const int HH[5] = {256,128,64,32,16};
    static const int WW[5] = {256,128,64,32,16};
    static const int BB[5] = {0,196608,245760,258048,261120};

    cudaFuncSetAttribute(conv3x3_kernel,
                         cudaFuncAttributeMaxDynamicSharedMemorySize, CONV_SMEM);
    cudaFuncSetAttribute(nms_kernel, cudaFuncAttributeMaxDynamicSharedMemorySize,
                         CAND_M * (int)sizeof(float));

    for (int l = 0; l < 5; ++l) {
        dim3 g(WW[l]/16, HH[l]/16, 8);
        conv3x3_kernel<<<g, 256, CONV_SMEM>>>(feats[l], conv_w, conv_b, HH[l], WW[l]);
        int px = 2 * HH[l] * WW[l];
        head1x1_kernel<<<(px + 255)/256, 256>>>(obj_w, obj_b, dl_w, dl_b,
                                                out, HH[l], WW[l], BB[l]);
    }
    select_kernel<<<6, 1024>>>();
    compact_kernel<<<10, 1024>>>(out);
    nms_kernel<<<2, 1024, CAND_M * sizeof(float)>>>(out);
}

// round 7
// speedup vs baseline: 3.7110x; 1.3367x over previous
#include <cuda_runtime.h>
#include <math.h>

#define ATOT   261888
#define CAND_M 21840
#define POSTK  1000
#define COMB   2618880
#define KB_OFF COMB
#define KS_OFF (COMB + 8000)
#define KV_OFF (COMB + 10000)
#define SCLAMP 4.135166556742356f
#define NEGINF (-__int_as_float(0x7f800000))

__constant__ int c_lvlbase[5] = {0,196608,245760,258048,261120};
__constant__ int c_lvlcnt[5]  = {196608,49152,12288,3072,768};
__constant__ int c_cslot[5]   = {0,6000,12000,18000,21072};
__constant__ int c_W[5]       = {256,128,64,32,16};
__constant__ int c_stride[5]  = {4,8,16,32,64};
__constant__ int c_size[5]    = {32,64,128,256,512};
__constant__ int c_toff[5]    = {0,33554432,41943040,44040192,44564480};
__constant__ int c_pxc[5]     = {131072,163840,172032,174080,174592};

__device__ float g_t[44695552];
__device__ float g_wT[589824];
__device__ float g_scores[2*ATOT];
__device__ float g_cscore[2*CAND_M];
__device__ float g_cbox[2*CAND_M*4];
__device__ float4 g_cobox[2*CAND_M];
__device__ float g_carea[2*CAND_M];
__device__ unsigned g_thr[6];
__device__ int g_need[6];

__device__ __forceinline__ unsigned fkey(float f) {
    unsigned u = __float_as_uint(f);
    return (u & 0x80000000u) ? ~u : (u | 0x80000000u);
}

// ---------------- weight transpose: [co][2304] -> [cb][kc][j][64co] ----------------
__global__ __launch_bounds__(1024) void wprep_kernel(const float* __restrict__ wgt) {
    int idx = blockIdx.x * 1024 + threadIdx.x;
    if (idx >= 589824) return;
    int co = idx & 63;
    int r  = idx >> 6;
    int j  = r % 144;
    int r2 = r / 144;
    int kc = r2 & 15, cb = r2 >> 4;
    g_wT[idx] = wgt[(size_t)(cb*64 + co)*2304 + kc*144 + j];
}

// ---------------- fused conv3x3 + bias + relu, all levels ----------------
// block: 256 thr; tile: 64 couts x 16x16 px. grid (341 tiles, 8 = n*4+cb)
#define CONV_SMEM ((16*9*64 + 16*360)*4)
__global__ __launch_bounds__(256, 2) void conv_fused_kernel(
    const float* __restrict__ f0, const float* __restrict__ f1,
    const float* __restrict__ f2, const float* __restrict__ f3,
    const float* __restrict__ f4, const float* __restrict__ bias)
{
    extern __shared__ float sm[];
    float* sW = sm;             // [j=ci*9+kk][64co]
    float* sI = sm + 9216;      // [ci][18][pitch20]

    const int tid = threadIdx.x;
    const int nb = blockIdx.y;
    const int n  = nb >> 2, cb = nb & 3;

    int bz = blockIdx.x, lvl, t;
    if      (bz < 256) { lvl = 0; t = bz;       }
    else if (bz < 320) { lvl = 1; t = bz - 256; }
    else if (bz < 336) { lvl = 2; t = bz - 320; }
    else if (bz < 340) { lvl = 3; t = bz - 336; }
    else               { lvl = 4; t = 0;        }
    const float* x = (lvl == 0) ? f0 : (lvl == 1) ? f1 : (lvl == 2) ? f2 : (lvl == 3) ? f3 : f4;
    const int W = c_W[lvl], H = W;
    const int tilesX = W >> 4;
    const int by = t / tilesX, bx = t - by * tilesX;
    const int h0 = by * 16, w0 = bx * 16;
    const int HW = H * W;
    float* tout = g_t + c_toff[lvl];

    const int tx = tid & 15, ty = tid >> 4;
    const int pr0 = (ty >> 2) * 4, pc0 = (ty & 3) * 4;

    float acc[4][16];
    #pragma unroll
    for (int q = 0; q < 4; ++q)
        #pragma unroll
        for (int j = 0; j < 16; ++j) acc[q][j] = 0.f;

    for (int kc = 0; kc < 16; ++kc) {
        // weights: contiguous 9216 floats for (cb,kc)
        const float4* wsrc = (const float4*)(g_wT + (size_t)(cb*16 + kc)*9216);
        #pragma unroll
        for (int it = 0; it < 9; ++it)
            ((float4*)sW)[tid + it*256] = wsrc[tid + it*256];
        // input: 16 cins x 18x18 (halo 1), pitch 20
        for (int i = tid; i < 16*18*18; i += 256) {
            int ci_l = i / 324; int p = i - ci_l*324;
            int r = p / 18, c = p - r*18;
            int gh = h0 - 1 + r, gw = w0 - 1 + c;
            float v = 0.f;
            if (gh >= 0 && gh < H && gw >= 0 && gw < W)
                v = x[(size_t)(n*256 + kc*16 + ci_l)*HW + gh*W + gw];
            sI[ci_l*360 + r*20 + c] = v;
        }
        __syncthreads();

        #pragma unroll 1
        for (int ci = 0; ci < 16; ++ci) {
            const float* ib = &sI[ci*360 + pr0*20 + pc0];
            const float* wb = &sW[ci*9*64 + tx*4];
            float in4[4][6];
            #pragma unroll
            for (int rr = 0; rr < 4; ++rr)
                #pragma unroll
                for (int cc = 0; cc < 6; ++cc)
                    in4[rr][cc] = ib[rr*20 + cc];
            #pragma unroll
            for (int kh = 0; kh < 3; ++kh) {
                #pragma unroll
                for (int kw = 0; kw < 3; ++kw) {
                    const float4 w4 = *(const float4*)&wb[(kh*3 + kw)*64];
                    #pragma unroll
                    for (int pr = 0; pr < 4; ++pr) {
                        #pragma unroll
                        for (int pc = 0; pc < 4; ++pc) {
                            float v = in4[pr][pc + kw];
                            acc[0][pr*4+pc] = fmaf(w4.x, v, acc[0][pr*4+pc]);
                            acc[1][pr*4+pc] = fmaf(w4.y, v, acc[1][pr*4+pc]);
                            acc[2][pr*4+pc] = fmaf(w4.z, v, acc[2][pr*4+pc]);
                            acc[3][pr*4+pc] = fmaf(w4.w, v, acc[3][pr*4+pc]);
                        }
                    }
                }
                if (kh < 2) {
                    #pragma unroll
                    for (int rr = 0; rr < 3; ++rr)
                        #pragma unroll
                        for (int cc = 0; cc < 6; ++cc)
                            in4[rr][cc] = in4[rr+1][cc];
                    #pragma unroll
                    for (int cc = 0; cc < 6; ++cc)
                        in4[3][cc] = ib[(4 + kh)*20 + cc];
                }
            }
        }
        __syncthreads();
    }

    #pragma unroll
    for (int q = 0; q < 4; ++q) {
        int co = cb*64 + tx*4 + q;
        float bv = __ldg(&bias[co]);
        #pragma unroll
        for (int pr = 0; pr < 4; ++pr) {
            float4 r;
            r.x = fmaxf(acc[q][pr*4+0] + bv, 0.f);
            r.y = fmaxf(acc[q][pr*4+1] + bv, 0.f);
            r.z = fmaxf(acc[q][pr*4+2] + bv, 0.f);
            r.w = fmaxf(acc[q][pr*4+3] + bv, 0.f);
            *(float4*)&tout[(size_t)(n*256 + co)*HW + (h0+pr0+pr)*W + w0+pc0] = r;
        }
    }
}

// ---------------- fused 1x1 heads, all levels ----------------
__global__ __launch_bounds__(256) void head_fused_kernel(
    const float* __restrict__ objw, const float* __restrict__ objb,
    const float* __restrict__ dlw,  const float* __restrict__ dlb,
    float* __restrict__ comb)
{
    __shared__ float sw[15*256];
    __shared__ float sb[15];
    int tid = threadIdx.x;
    for (int i = tid; i < 3*256; i += 256)  sw[i] = objw[i];
    for (int i = tid; i < 12*256; i += 256) sw[768 + i] = dlw[i];
    if (tid < 3)  sb[tid] = objb[tid];
    if (tid >= 3 && tid < 15) sb[tid] = dlb[tid - 3];
    __syncthreads();

    int pid = blockIdx.x * 256 + tid;
    if (pid >= 174592) return;
    int lvl, start;
    if      (pid < c_pxc[0]) { lvl = 0; start = 0; }
    else if (pid < c_pxc[1]) { lvl = 1; start = c_pxc[0]; }
    else if (pid < c_pxc[2]) { lvl = 2; start = c_pxc[1]; }
    else if (pid < c_pxc[3]) { lvl = 3; start = c_pxc[2]; }
    else                     { lvl = 4; start = c_pxc[3]; }
    int q = pid - start;
    int Wl = c_W[lvl];
    int HW = Wl * Wl;
    int n = q / HW, hw = q - n*HW;
    int gbase = c_lvlbase[lvl];

    float acc[15];
    #pragma unroll
    for (int k = 0; k < 15; ++k) acc[k] = sb[k];
    const float* tp = g_t + c_toff[lvl] + (size_t)n*256*HW + hw;
    #pragma unroll 4
    for (int c = 0; c < 256; ++c) {
        float tv = __ldg(&tp[(size_t)c * HW]);
        #pragma unroll
        for (int k = 0; k < 15; ++k) acc[k] = fmaf(tv, sw[k*256 + c], acc[k]);
    }
    #pragma unroll
    for (int a = 0; a < 3; ++a) {
        int ga = gbase + hw*3 + a;
        size_t o = ((size_t)n*ATOT + ga)*5;
        comb[o]   = acc[a];
        comb[o+1] = acc[3 + a*4 + 0];
        comb[o+2] = acc[3 + a*4 + 1];
        comb[o+3] = acc[3 + a*4 + 2];
        comb[o+4] = acc[3 + a*4 + 3];
        g_scores[(size_t)n*ATOT + ga] = acc[a];
    }
}

// ---------------- exact top-6000 threshold (radix refine) ----------------
__global__ __launch_bounds__(1024) void select_kernel() {
    int task = blockIdx.x;
    int n = task / 3, lvl = task % 3;
    const float* d = g_scores + (size_t)n*ATOT + c_lvlbase[lvl];
    int cnt = c_lvlcnt[lvl];
    int tid = threadIdx.x;
    __shared__ int hist[256];
    __shared__ unsigned s_prefix;
    __shared__ int s_Kr;
    if (tid == 0) { s_prefix = 0; s_Kr = 6000; }
    __syncthreads();
    for (int pass = 0; pass < 4; ++pass) {
        int shift = 24 - pass*8;
        if (tid < 256) hist[tid] = 0;
        __syncthreads();
        unsigned pref = s_prefix;
        for (int i = tid; i < cnt; i += 1024) {
            unsigned k = fkey(d[i]);
            bool in = (pass == 0) || ((k >> (shift + 8)) == pref);
            if (in) atomicAdd(&hist[(k >> shift) & 255], 1);
        }
        __syncthreads();
        if (tid == 0) {
            int run = 0, dd = 255;
            for (dd = 255; dd >= 0; --dd) {
                if (run + hist[dd] >= s_Kr) break;
                run += hist[dd];
            }
            s_prefix = (s_prefix << 8) | (unsigned)dd;
            s_Kr -= run;
        }
        __syncthreads();
    }
    if (tid == 0) { g_thr[task] = s_prefix; g_need[task] = s_Kr; }
}

// ---------------- stable compaction + decode ----------------
__device__ __forceinline__ int blockScan01(int pred, int tid, int* ws, int* tot) {
    unsigned b = __ballot_sync(0xffffffffu, pred != 0);
    int lane = tid & 31, wid = tid >> 5;
    int lpre = __popc(b & ((1u << lane) - 1u));
    if (lane == 0) ws[wid] = __popc(b);
    __syncthreads();
    if (tid < 32) {
        int v = ws[tid];
        int s = v;
        #pragma unroll
        for (int o = 1; o < 32; o <<= 1) {
            int t = __shfl_up_sync(0xffffffffu, s, o);
            if (tid >= o) s += t;
        }
        ws[tid] = s - v;
        if (tid == 31) ws[32] = s;
    }
    __syncthreads();
    int ex = ws[wid] + lpre;
    *tot = ws[32];
    __syncthreads();
    return ex;
}

__global__ __launch_bounds__(1024) void compact_kernel(const float* __restrict__ comb) {
    int n = blockIdx.x / 5, lvl = blockIdx.x % 5;
    int tid = threadIdx.x;
    __shared__ int ws[33];
    unsigned T = 0; int need = 0;
    if (lvl < 3) { T = g_thr[n*3 + lvl]; need = g_need[n*3 + lvl]; }
    const float* sc = g_scores + (size_t)n*ATOT + c_lvlbase[lvl];
    int cnt = c_lvlcnt[lvl];
    int outBase = n*CAND_M + c_cslot[lvl];
    int gbase = c_lvlbase[lvl];
    int Wl = c_W[lvl], str = c_stride[lvl];
    double sz = (double)c_size[lvl];
    int eqBefore = 0, written = 0;
    for (int start = 0; start < cnt; start += 1024) {
        int i = start + tid;
        bool inb = (i < cnt);
        unsigned k = inb ? fkey(sc[i]) : 0u;
        int pEQ = (inb && k == T) ? 1 : 0;
        int totEQ; int exEQ = blockScan01(pEQ, tid, ws, &totEQ);
        int sel = (inb && (k > T || (pEQ && (eqBefore + exEQ) < need))) ? 1 : 0;
        int totS; int exS = blockScan01(sel, tid, ws, &totS);
        if (sel) {
            int slot = outBase + written + exS;
            int hw = i / 3, a = i - hw*3;
            int h = hw / Wl, w = hw - h*Wl;
            double r = (a == 0) ? 0.5 : ((a == 1) ? 1.0 : 2.0);
            double wsd = sqrt(sz*sz/r);
            double hsd = wsd*r;
            double xx = (double)(w * str), yy = (double)(h * str);
            float a0 = (float)(xx - wsd*0.5);
            float a1 = (float)(yy - hsd*0.5);
            float a2 = (float)(xx + wsd*0.5);
            float a3 = (float)(yy + hsd*0.5);
            size_t o = ((size_t)n*ATOT + gbase + i)*5;
            float dx = comb[o+1], dy = comb[o+2];
            float dw = fminf(comb[o+3], SCLAMP), dh = fminf(comb[o+4], SCLAMP);
            float aw = a2 - a0, ah = a3 - a1;
            float cx = a0 + 0.5f*aw, cy = a1 + 0.5f*ah;
            float pcx = dx*aw + cx, pcy = dy*ah + cy;
            float pw = expf(dw)*aw, ph = expf(dh)*ah;
            float x1 = pcx - 0.5f*pw, y1 = pcy - 0.5f*ph;
            float x2 = pcx + 0.5f*pw, y2 = pcy + 0.5f*ph;
            x1 = fminf(fmaxf(x1, 0.f), 1024.f);
            y1 = fminf(fmaxf(y1, 0.f), 1024.f);
            x2 = fminf(fmaxf(x2, 0.f), 1024.f);
            y2 = fminf(fmaxf(y2, 0.f), 1024.f);
            g_cbox[slot*4+0] = x1; g_cbox[slot*4+1] = y1;
            g_cbox[slot*4+2] = x2; g_cbox[slot*4+3] = y2;
            float off = (float)lvl * 2000.0f;
            float o0 = x1 + off, o1 = y1 + off, o2 = x2 + off, o3 = y2 + off;
            g_cobox[slot] = make_float4(o0, o1, o2, o3);
            g_carea[slot] = (o2 - o0) * (o3 - o1);
            g_cscore[slot] = sc[i];
        }
        eqBefore += totEQ; written += totS;
    }
}

// ---------------- argmax-NMS (exact scan semantics) ----------------
__global__ __launch_bounds__(1024) void nms_kernel(float* __restrict__ out) {
    extern __shared__ float s[];
    __shared__ float rv[32]; __shared__ int ri[32];
    __shared__ float s_bv; __shared__ int s_bi; __shared__ int s_fb;
    int n = blockIdx.x, tid = threadIdx.x;
    int base = n * CAND_M;
    for (int j = tid; j < CAND_M; j += 1024) s[j] = g_cscore[base + j];
    __syncthreads();

    {
        float bv = NEGINF; int bi = 0x7fffffff;
        for (int j = tid; j < 6000; j += 1024) {
            float v = s[j];
            if (v > bv) { bv = v; bi = j; }
            else if (v == bv && j < bi) bi = j;
        }
        #pragma unroll
        for (int o = 16; o; o >>= 1) {
            float ov = __shfl_down_sync(0xffffffffu, bv, o);
            int oi = __shfl_down_sync(0xffffffffu, bi, o);
            if (ov > bv || (ov == bv && oi < bi)) { bv = ov; bi = oi; }
        }
        if ((tid & 31) == 0) { rv[tid >> 5] = bv; ri[tid >> 5] = bi; }
        __syncthreads();
        if (tid < 32) {
            bv = rv[tid]; bi = ri[tid];
            #pragma unroll
            for (int o = 16; o; o >>= 1) {
                float ov = __shfl_down_sync(0xffffffffu, bv, o);
                int oi = __shfl_down_sync(0xffffffffu, bi, o);
                if (ov > bv || (ov == bv && oi < bi)) { bv = ov; bi = oi; }
            }
            if (tid == 0) s_fb = bi;
        }
        __syncthreads();
    }

    float* kb = out + KB_OFF + (size_t)n*POSTK*4;
    float* ks = out + KS_OFF + (size_t)n*POSTK;
    float* kv = out + KV_OFF + (size_t)n*POSTK;

    for (int iter = 0; iter < POSTK; ++iter) {
        float bv = NEGINF; int bi = 0x7fffffff;
        for (int j = tid; j < CAND_M; j += 1024) {
            float v = s[j];
            if (v > bv) { bv = v; bi = j; }
            else if (v == bv && j < bi) bi = j;
        }
        #pragma unroll
        for (int o = 16; o; o >>= 1) {
            float ov = __shfl_down_sync(0xffffffffu, bv, o);
            int oi = __shfl_down_sync(0xffffffffu, bi, o);
            if (ov > bv || (ov == bv && oi < bi)) { bv = ov; bi = oi; }
        }
        if ((tid & 31) == 0) { rv[tid >> 5] = bv; ri[tid >> 5] = bi; }
        __syncthreads();
        if (tid < 32) {
            bv = rv[tid]; bi = ri[tid];
            #pragma unroll
            for (int o = 16; o; o >>= 1) {
                float ov = __shfl_down_sync(0xffffffffu, bv, o);
                int oi = __shfl_down_sync(0xffffffffu, bi, o);
                if (ov > bv || (ov == bv && oi < bi)) { bv = ov; bi = oi; }
            }
            if (tid == 0) { s_bv = bv; s_bi = bi; }
        }
        __syncthreads();
        bv = s_bv; bi = s_bi;
        bool valid = (bv > NEGINF);
        int src = valid ? bi : s_fb;
        if (tid == 0) {
            kb[iter*4+0] = g_cbox[(base+src)*4+0];
            kb[iter*4+1] = g_cbox[(base+src)*4+1];
            kb[iter*4+2] = g_cbox[(base+src)*4+2];
            kb[iter*4+3] = g_cbox[(base+src)*4+3];
            ks[iter] = g_cscore[base+src];
            kv[iter] = valid ? 1.0f : 0.0f;
        }
        if (valid) {
            int segLo, segHi;
            if      (bi < 6000)  { segLo = 0;     segHi = 6000;  }
            else if (bi < 12000) { segLo = 6000;  segHi = 12000; }
            else if (bi < 18000) { segLo = 12000; segHi = 18000; }
            else if (bi < 21072) { segLo = 18000; segHi = 21072; }
            else                 { segLo = 21072; segHi = 21840; }
            float4 bb = g_cobox[base + bi];
            float ai = g_carea[base + bi];
            for (int j = segLo + tid; j < segHi; j += 1024) {
                float v = s[j];
                if (v > NEGINF) {
                    float4 cj = g_cobox[base + j];
                    float x1 = fmaxf(bb.x, cj.x), y1 = fmaxf(bb.y, cj.y);
                    float x2 = fminf(bb.z, cj.z), y2 = fminf(bb.w, cj.w);
                    float inter = fmaxf(x2 - x1, 0.f) * fmaxf(y2 - y1, 0.f);
                    float iou = inter / (ai + g_carea[base + j] - inter + 1e-9f);
                    if (iou > 0.7f) s[j] = NEGINF;
                }
            }
        }
        if (tid == 0) s[bi] = NEGINF;
        __syncthreads();
    }
}

extern "C" void kernel_launch(void* const* d_in, const int* in_sizes, int n_in,
                              void* d_out, int out_size) {
    const float* f0 = (const float*)d_in[0];
    const float* f1 = (const float*)d_in[1];
    const float* f2 = (const float*)d_in[2];
    const float* f3 = (const float*)d_in[3];
    const float* f4 = (const float*)d_in[4];
    const float* conv_w = (const float*)d_in[5];
    const float* conv_b = (const float*)d_in[6];
    const float* obj_w  = (const float*)d_in[7];
    const float* obj_b  = (const float*)d_in[8];
    const float* dl_w   = (const float*)d_in[9];
    const float* dl_b   = (const float*)d_in[10];
    float* out = (float*)d_out;

    cudaFuncSetAttribute(conv_fused_kernel,
                         cudaFuncAttributeMaxDynamicSharedMemorySize, CONV_SMEM);
    cudaFuncSetAttribute(nms_kernel, cudaFuncAttributeMaxDynamicSharedMemorySize,
                         CAND_M * (int)sizeof(float));

    wprep_kernel<<<576, 1024>>>(conv_w);
    conv_fused_kernel<<<dim3(341, 8), 256, CONV_SMEM>>>(f0, f1, f2, f3, f4, conv_b);
    head_fused_kernel<<<682, 256>>>(obj_w, obj_b, dl_w, dl_b, out);
    select_kernel<<<6, 1024>>>();
    compact_kernel<<<10, 1024>>>(out);
    nms_kernel<<<2, 1024, CAND_M * sizeof(float)>>>(out);
}